// round 15
// baseline (speedup 1.0000x reference)
#include <cuda_runtime.h>
#include <cuda_fp16.h>
#include <cstdint>
#include <math.h>

#define B_   8
#define N_   4096
#define K_   32
#define C_   128
#define O_   64
#define NH_  80
#define TN_  4
#define M2_  128            // positions per tile
#define NT_  256            // threads per block
#define NBLK 304            // persistent CTAs (2 per SM x 152)
#define TILES 8192          // B_ * N_ / TN_

// ---- smem layout (bytes) ----
#define SM_W    0           // W hi (80x128 fp16, 20480) + W lo for o>=64 (16x128, 4096)
#define SM_WLO  20480
#define SM_XB   24576       // 2 bufs x 32768: 64c x 128m fp16 (hi 16384 + lo 16384)
#define SM_WFS  90112       // 128 floats
#define SM_OBUF 90624       // 64 x 5 floats = 1280
#define SM_TOTAL 92160

__device__ __forceinline__ uint32_t smem_u32(const void* p) {
    uint32_t a;
    asm("{ .reg .u64 t; cvta.to.shared.u64 t, %1; cvt.u32.u64 %0, t; }" : "=r"(a) : "l"(p));
    return a;
}

#define LDSM_X4(r, a) \
    asm volatile("ldmatrix.sync.aligned.m8n8.x4.shared.b16 {%0,%1,%2,%3}, [%4];" \
        : "=r"((r)[0]), "=r"((r)[1]), "=r"((r)[2]), "=r"((r)[3]) : "r"(a))
#define LDSM_X4_T(r, a) \
    asm volatile("ldmatrix.sync.aligned.m8n8.x4.trans.shared.b16 {%0,%1,%2,%3}, [%4];" \
        : "=r"((r)[0]), "=r"((r)[1]), "=r"((r)[2]), "=r"((r)[3]) : "r"(a))
#define MMA_F16(c, a, b0, b1) \
    asm volatile("mma.sync.aligned.m16n8k16.row.col.f32.f16.f16.f32 " \
        "{%0,%1,%2,%3},{%4,%5,%6,%7},{%8,%9},{%0,%1,%2,%3};" \
        : "+f"((c)[0]), "+f"((c)[1]), "+f"((c)[2]), "+f"((c)[3]) \
        : "r"((a)[0]), "r"((a)[1]), "r"((a)[2]), "r"((a)[3]), "r"(b0), "r"(b1))

// ================= weight prep (same image as R7-R14) =================
__device__ uint4 g_Wimg[1536];   // 24576 B

__global__ void prep_b(const float* __restrict__ wt, const float* __restrict__ wg,
                       const float* __restrict__ wa) {
    int i = blockIdx.x * blockDim.x + threadIdx.x;
    if (i >= NH_ * C_) return;
    int o = i >> 7, c = i & 127;
    float w = (o < 64) ? wt[o * C_ + c]
            : (o < 72) ? wg[(o - 64) * C_ + c]
                       : wa[(o - 72) * C_ + c];
    __half h = __float2half_rn(w);
    unsigned inner = ((((unsigned)(c >> 3) ^ (o & 7)) << 4)) + (c & 7) * 2u;
    __half* base = (__half*)g_Wimg;
    base[((unsigned)o * 256u + inner) >> 1] = h;
    if (o >= 64) {
        __half l = __float2half_rn(w - __half2float(h));
        base[(20480u + (unsigned)(o - 64) * 256u + inner) >> 1] = l;
    }
}

// STS one 64c x 128m chunk (hi+lo fp16 planes), 8 c-rows per thread
__device__ __forceinline__ void sts_chunk64(char* base, const float4* stg, int crow, int q) {
    #pragma unroll
    for (int it = 0; it < 8; it++) {
        int c = crow + it * 8;
        float4 v = stg[it];
        __half h0 = __float2half_rn(v.x), h1 = __float2half_rn(v.y);
        __half h2 = __float2half_rn(v.z), h3 = __float2half_rn(v.w);
        __half l0 = __float2half_rn(v.x - __half2float(h0));
        __half l1 = __float2half_rn(v.y - __half2float(h1));
        __half l2 = __float2half_rn(v.z - __half2float(h2));
        __half l3 = __float2half_rn(v.w - __half2float(h3));
        uint2 ph, pl;
        ph.x = (uint32_t)__half_as_ushort(h0) | ((uint32_t)__half_as_ushort(h1) << 16);
        ph.y = (uint32_t)__half_as_ushort(h2) | ((uint32_t)__half_as_ushort(h3) << 16);
        pl.x = (uint32_t)__half_as_ushort(l0) | ((uint32_t)__half_as_ushort(l1) << 16);
        pl.y = (uint32_t)__half_as_ushort(l2) | ((uint32_t)__half_as_ushort(l3) << 16);
        unsigned off = (unsigned)c * 256u + ((((unsigned)(q >> 1)) ^ (c & 7)) << 4) + (q & 1) * 8u;
        *(uint2*)(base + off) = ph;
        *(uint2*)(base + 16384 + off) = pl;
    }
}

// ================= main kernel (persistent, 64c steps) =================
__global__ __launch_bounds__(NT_, 2)
void gsl_mma(const float* __restrict__ x,
             const float* __restrict__ g_trans, const float* __restrict__ b_trans,
             const float* __restrict__ g_gate,  const float* __restrict__ b_gate,
             const float* __restrict__ w_gate2, const float* __restrict__ b_gate2,
             const float* __restrict__ g_attn,  const float* __restrict__ b_attn,
             const float* __restrict__ w_attn2, const float* __restrict__ b_attn2,
             const float* __restrict__ agg_alpha,
             float* __restrict__ out, float* __restrict__ gate_out)
{
    extern __shared__ char smem[];
    const uint32_t sb = smem_u32(smem);
    const int t    = threadIdx.x;
    const int wid  = t >> 5;
    const int lane = t & 31;
    const int mw   = wid & 3;       // n-row within tile (4 rows)
    const int nw   = wid >> 2;      // 0: o 0..47, 1: o 48..79 (+heads)
    const int crow = t >> 5;        // 0..7: c row (mod 8) for staging
    const int q32  = t & 31;        // 16B group within 128m row
    const int bid  = blockIdx.x;

    // ---- fragment addressing (tile-invariant) ----
    const int l7   = lane & 7;
    const int koff = (lane >> 3) & 1;
    const int r16  = l7 + ((lane & 16) >> 1);
    uint32_t aBase[2];
    #pragma unroll
    for (int mt = 0; mt < 2; mt++)
        aBase[mt] = sb + SM_XB + r16 * 256 + ((((unsigned)(4 * mw + 2 * mt + koff)) ^ l7) << 4);
    const uint32_t bRowHi = sb + SM_W + r16 * 256;
    const uint32_t bRowLo = sb + SM_WLO + r16 * 256;

    const int qg = lane >> 2;
    const int c4 = lane & 3;
    float* WFs  = (float*)(smem + SM_WFS);
    float* Obuf = (float*)(smem + SM_OBUF);

    // ---- load W image once per CTA ----
    {
        uint4 wstg[6];
        #pragma unroll
        for (int i = 0; i < 6; i++) wstg[i] = g_Wimg[t + NT_ * i];
        uint4* d = (uint4*)smem;
        #pragma unroll
        for (int i = 0; i < 6; i++) d[t + NT_ * i] = wstg[i];
    }
    const float alpha = 1.0f / (1.0f + __expf(-agg_alpha[0]));

    // ---- LDG of 64c chunk lc into an 8x float4 register set ----
    auto ldg_chunk = [&](int lc, float4* stg) {
        int tl = bid + (lc >> 1) * NBLK;
        if (tl >= TILES) tl = bid;                    // clamped redundant load (tail)
        const float* src = x + (tl >> 10) * (C_ * N_ * K_) + (tl & 1023) * (TN_ * K_) + q32 * 4;
        const int cb = (lc & 1) * 64 + crow;
        #pragma unroll
        for (int i = 0; i < 8; i++)
            stg[i] = *(const float4*)(src + (size_t)(cb + 8 * i) * (N_ * K_));
    };

    // ---- prologue: chunk 0 -> buf 0 ----
    float4 stg[8];
    ldg_chunk(0, stg);
    int lc = 1;                      // next chunk to LDG
    sts_chunk64(smem + SM_XB, stg, crow, q32);
    __syncthreads();

    // ================= persistent tile loop =================
    for (int tile = bid; tile < TILES; tile += NBLK) {
        const int b  = tile >> 10;
        const int nb = (tile & 1023) * TN_;

        float acc[2][6][4];
        #pragma unroll
        for (int mt = 0; mt < 2; mt++)
            #pragma unroll
            for (int i = 0; i < 6; i++)
                #pragma unroll
                for (int j = 0; j < 4; j++) acc[mt][i][j] = 0.0f;

        // ---- mainloop: 2 steps of 64 c ----
        // invariant top of step s: buf s&1 ready (MMA input)
        #pragma unroll
        for (int s = 0; s < 2; s++) {
            // LDG chunk s+1 (for s=1: next tile's first chunk)
            ldg_chunk(lc, stg);
            lc++;

            // MMA on fp16 buffer s&1 (4 x 16c sub-steps)
            const uint32_t xb = (uint32_t)(s & 1) * 32768u;
            #pragma unroll
            for (int g = 0; g < 4; g++) {
                const int st16 = 4 * s + g;
                const uint32_t cs = ((((unsigned)(2 * st16 + koff)) ^ l7) << 4);
                uint32_t ah[2][4];
                #pragma unroll
                for (int mt = 0; mt < 2; mt++)
                    LDSM_X4_T(ah[mt], aBase[mt] + xb + g * 4096u);
                if (nw == 0) {
                    #pragma unroll
                    for (int jp = 0; jp < 3; jp++) {
                        uint32_t bh[4];
                        LDSM_X4(bh, bRowHi + jp * 4096 + cs);
                        #pragma unroll
                        for (int mt = 0; mt < 2; mt++) {
                            MMA_F16(acc[mt][2 * jp],     ah[mt], bh[0], bh[1]);
                            MMA_F16(acc[mt][2 * jp + 1], ah[mt], bh[2], bh[3]);
                        }
                    }
                } else {
                    uint32_t al[2][4];
                    #pragma unroll
                    for (int mt = 0; mt < 2; mt++)
                        LDSM_X4_T(al[mt], aBase[mt] + xb + g * 4096u + 16384u);
                    {
                        uint32_t bh[4];
                        LDSM_X4(bh, bRowHi + 3 * 4096 + cs);
                        #pragma unroll
                        for (int mt = 0; mt < 2; mt++) {
                            MMA_F16(acc[mt][0], ah[mt], bh[0], bh[1]);
                            MMA_F16(acc[mt][1], ah[mt], bh[2], bh[3]);
                        }
                    }
                    {
                        uint32_t bh[4], bl[4];
                        LDSM_X4(bh, bRowHi + 4 * 4096 + cs);
                        LDSM_X4(bl, bRowLo + cs);
                        #pragma unroll
                        for (int mt = 0; mt < 2; mt++) {
                            MMA_F16(acc[mt][2], ah[mt], bh[0], bh[1]);
                            MMA_F16(acc[mt][3], ah[mt], bh[2], bh[3]);
                            MMA_F16(acc[mt][2], al[mt], bh[0], bh[1]);
                            MMA_F16(acc[mt][3], al[mt], bh[2], bh[3]);
                            MMA_F16(acc[mt][2], ah[mt], bl[0], bl[1]);
                            MMA_F16(acc[mt][3], ah[mt], bl[2], bl[3]);
                        }
                    }
                }
            }

            // convert chunk s+1 -> fp16 buf (s+1)&1
            sts_chunk64(smem + SM_XB + (((s + 1) & 1) ? 32768 : 0), stg, crow, q32);
            __syncthreads();
        }

        // ================= in-register epilogue (R10-R14 verbatim) =================
        float WFreg[2][2];

        if (nw == 1) {
            float gl[2][2], al[2][2];
            const float bg2 = b_gate2[0], ba2 = b_attn2[0];
            #pragma unroll
            for (int mt = 0; mt < 2; mt++)
                #pragma unroll
                for (int rh = 0; rh < 2; rh++) {
                    float glp = 0.0f, alp = 0.0f;
                    #pragma unroll
                    for (int j = 0; j < 2; j++) {
                        int oc = 2 * c4 + j;
                        float yg = acc[mt][2][2 * rh + j];
                        float v = fmaf(g_gate[oc], yg, b_gate[oc]);
                        v = (v >= 0.0f) ? v : 0.2f * v;
                        glp = fmaf(w_gate2[oc], v, glp);
                        float ya = acc[mt][3][2 * rh + j];
                        float u = fmaf(g_attn[oc], ya, b_attn[oc]);
                        u = (u >= 0.0f) ? u : 0.2f * u;
                        alp = fmaf(w_attn2[oc], u, alp);
                    }
                    glp += __shfl_xor_sync(0xffffffffu, glp, 1);
                    glp += __shfl_xor_sync(0xffffffffu, glp, 2);
                    alp += __shfl_xor_sync(0xffffffffu, alp, 1);
                    alp += __shfl_xor_sync(0xffffffffu, alp, 2);
                    gl[mt][rh] = glp + bg2;
                    al[mt][rh] = alp + ba2;
                }
            float amax = fmaxf(fmaxf(al[0][0], al[0][1]), fmaxf(al[1][0], al[1][1]));
            #pragma unroll
            for (int s = 4; s <= 16; s <<= 1)
                amax = fmaxf(amax, __shfl_xor_sync(0xffffffffu, amax, s));
            float e[2][2];
            float S = 0.0f;
            #pragma unroll
            for (int mt = 0; mt < 2; mt++)
                #pragma unroll
                for (int rh = 0; rh < 2; rh++) {
                    e[mt][rh] = __expf(al[mt][rh] - amax);
                    S += e[mt][rh];
                }
            #pragma unroll
            for (int s = 4; s <= 16; s <<= 1)
                S += __shfl_xor_sync(0xffffffffu, S, s);
            const float invS = 1.0f / S;
            float wm[2][2];
            float Sm = 0.0f;
            #pragma unroll
            for (int mt = 0; mt < 2; mt++)
                #pragma unroll
                for (int rh = 0; rh < 2; rh++) {
                    float w = e[mt][rh] * invS;
                    wm[mt][rh] = (gl[mt][rh] >= 0.0f) ? w : 0.0f;
                    Sm += wm[mt][rh];
                }
            #pragma unroll
            for (int s = 4; s <= 16; s <<= 1)
                Sm += __shfl_xor_sync(0xffffffffu, Sm, s);
            const float rn = 1.0f / (Sm + 1e-6f);
            #pragma unroll
            for (int mt = 0; mt < 2; mt++)
                #pragma unroll
                for (int rh = 0; rh < 2; rh++)
                    WFreg[mt][rh] = wm[mt][rh] * rn;
            if (c4 == 0) {
                const int gbase = b * (N_ * K_) + (nb + mw) * K_;
                #pragma unroll
                for (int mt = 0; mt < 2; mt++)
                    #pragma unroll
                    for (int rh = 0; rh < 2; rh++) {
                        int k = qg + 8 * rh + 16 * mt;
                        WFs[mw * 32 + k] = WFreg[mt][rh];
                        gate_out[gbase + k] = gl[mt][rh];
                    }
            }
        }
        __syncthreads();

        if (nw == 0) {
            #pragma unroll
            for (int mt = 0; mt < 2; mt++)
                #pragma unroll
                for (int rh = 0; rh < 2; rh++)
                    WFreg[mt][rh] = WFs[mw * 32 + qg + 8 * rh + 16 * mt];
        }

        {
            const int ob  = nw * 48;
            const int njj = nw ? 2 : 6;
            for (int jj = 0; jj < njj; jj++) {
                #pragma unroll
                for (int par = 0; par < 2; par++) {
                    const int o = ob + 8 * jj + 2 * c4 + par;
                    const float g  = g_trans[o];
                    const float bb = b_trans[o];
                    float s = 0.0f, mx = -INFINITY;
                    #pragma unroll
                    for (int mt = 0; mt < 2; mt++)
                        #pragma unroll
                        for (int rh = 0; rh < 2; rh++) {
                            float y  = acc[mt][jj][2 * rh + par];
                            float tv = fmaf(g, y, bb);
                            tv = (tv >= 0.0f) ? tv : 0.2f * tv;
                            s  = fmaf(tv, WFreg[mt][rh], s);
                            mx = fmaxf(mx, tv);
                        }
                    #pragma unroll
                    for (int st = 4; st <= 16; st <<= 1) {
                        s += __shfl_xor_sync(0xffffffffu, s, st);
                        mx = fmaxf(mx, __shfl_xor_sync(0xffffffffu, mx, st));
                    }
                    if (qg == 0)
                        Obuf[o * 5 + mw] = alpha * s + (1.0f - alpha) * mx;
                }
            }
        }
        __syncthreads();

        if (t < 64) {
            float4 v;
            v.x = Obuf[t * 5 + 0];
            v.y = Obuf[t * 5 + 1];
            v.z = Obuf[t * 5 + 2];
            v.w = Obuf[t * 5 + 3];
            *(float4*)(out + (b * O_ + t) * N_ + nb) = v;
        }
        // no tail barrier: next writes to WFs/Obuf are >=2 barriers away
    }
}

extern "C" void kernel_launch(void* const* d_in, const int* in_sizes, int n_in,
                              void* d_out, int out_size) {
    const float* x        = (const float*)d_in[0];
    const float* w_trans  = (const float*)d_in[1];
    const float* g_trans  = (const float*)d_in[2];
    const float* b_trans  = (const float*)d_in[3];
    const float* w_gate1  = (const float*)d_in[4];
    const float* g_gate   = (const float*)d_in[5];
    const float* b_gate   = (const float*)d_in[6];
    const float* w_gate2  = (const float*)d_in[7];
    const float* b_gate2  = (const float*)d_in[8];
    const float* w_attn1  = (const float*)d_in[9];
    const float* g_attn   = (const float*)d_in[10];
    const float* b_attn   = (const float*)d_in[11];
    const float* w_attn2  = (const float*)d_in[12];
    const float* b_attn2  = (const float*)d_in[13];
    const float* agg_alpha= (const float*)d_in[14];

    float* out      = (float*)d_out;                  // [B,O,N]
    float* gate_out = out + (size_t)B_ * O_ * N_;     // [B,1,N,K]

    cudaFuncSetAttribute(gsl_mma, cudaFuncAttributeMaxDynamicSharedMemorySize, SM_TOTAL);

    prep_b<<<(NH_ * C_ + 255) / 256, 256>>>(w_trans, w_gate1, w_attn1);
    gsl_mma<<<NBLK, NT_, SM_TOTAL>>>(
        x, g_trans, b_trans, g_gate, b_gate, w_gate2, b_gate2,
        g_attn, b_attn, w_attn2, b_attn2, agg_alpha, out, gate_out);
}

// round 16
// speedup vs baseline: 1.1229x; 1.1229x over previous
#include <cuda_runtime.h>
#include <cuda_fp16.h>
#include <cstdint>
#include <math.h>

#define B_   8
#define N_   4096
#define K_   32
#define C_   128
#define O_   64
#define NH_  80
#define TN_  4
#define M2_  128            // positions per tile
#define NT_  256            // threads per block
#define NBLK 304            // persistent CTAs (2 per SM x 152)
#define TILES 8192          // B_ * N_ / TN_

// ---- smem layout (bytes) ----
#define SM_W    0           // W hi (80x128 fp16, 20480) + W lo for o>=64 (16x128, 4096)
#define SM_WLO  20480
#define SM_XB   24576       // 2 bufs x 16384: 32c x 128m fp16 (hi 8192 + lo 8192)
#define SM_WFS  57344       // 128 floats
#define SM_OBUF 57856       // 64 x 5 floats = 1280
#define SM_TOTAL 59392

__device__ __forceinline__ uint32_t smem_u32(const void* p) {
    uint32_t a;
    asm("{ .reg .u64 t; cvta.to.shared.u64 t, %1; cvt.u32.u64 %0, t; }" : "=r"(a) : "l"(p));
    return a;
}

#define LDSM_X4(r, a) \
    asm volatile("ldmatrix.sync.aligned.m8n8.x4.shared.b16 {%0,%1,%2,%3}, [%4];" \
        : "=r"((r)[0]), "=r"((r)[1]), "=r"((r)[2]), "=r"((r)[3]) : "r"(a))
#define LDSM_X4_T(r, a) \
    asm volatile("ldmatrix.sync.aligned.m8n8.x4.trans.shared.b16 {%0,%1,%2,%3}, [%4];" \
        : "=r"((r)[0]), "=r"((r)[1]), "=r"((r)[2]), "=r"((r)[3]) : "r"(a))
#define MMA_F16(c, a, b0, b1) \
    asm volatile("mma.sync.aligned.m16n8k16.row.col.f32.f16.f16.f32 " \
        "{%0,%1,%2,%3},{%4,%5,%6,%7},{%8,%9},{%0,%1,%2,%3};" \
        : "+f"((c)[0]), "+f"((c)[1]), "+f"((c)[2]), "+f"((c)[3]) \
        : "r"((a)[0]), "r"((a)[1]), "r"((a)[2]), "r"((a)[3]), "r"(b0), "r"(b1))

// ================= weight prep (same image as R7-R15) =================
__device__ uint4 g_Wimg[1536];   // 24576 B

__global__ void prep_b(const float* __restrict__ wt, const float* __restrict__ wg,
                       const float* __restrict__ wa) {
    int i = blockIdx.x * blockDim.x + threadIdx.x;
    if (i >= NH_ * C_) return;
    int o = i >> 7, c = i & 127;
    float w = (o < 64) ? wt[o * C_ + c]
            : (o < 72) ? wg[(o - 64) * C_ + c]
                       : wa[(o - 72) * C_ + c];
    __half h = __float2half_rn(w);
    unsigned inner = ((((unsigned)(c >> 3) ^ (o & 7)) << 4)) + (c & 7) * 2u;
    __half* base = (__half*)g_Wimg;
    base[((unsigned)o * 256u + inner) >> 1] = h;
    if (o >= 64) {
        __half l = __float2half_rn(w - __half2float(h));
        base[(20480u + (unsigned)(o - 64) * 256u + inner) >> 1] = l;
    }
}

// STS one 32c x 128m chunk (hi+lo fp16 planes), 4 c-rows per thread
__device__ __forceinline__ void sts_chunk(char* base, const float4* stg, int crow, int q) {
    #pragma unroll
    for (int it = 0; it < 4; it++) {
        int c = crow + it * 8;
        float4 v = stg[it];
        __half h0 = __float2half_rn(v.x), h1 = __float2half_rn(v.y);
        __half h2 = __float2half_rn(v.z), h3 = __float2half_rn(v.w);
        __half l0 = __float2half_rn(v.x - __half2float(h0));
        __half l1 = __float2half_rn(v.y - __half2float(h1));
        __half l2 = __float2half_rn(v.z - __half2float(h2));
        __half l3 = __float2half_rn(v.w - __half2float(h3));
        uint2 ph, pl;
        ph.x = (uint32_t)__half_as_ushort(h0) | ((uint32_t)__half_as_ushort(h1) << 16);
        ph.y = (uint32_t)__half_as_ushort(h2) | ((uint32_t)__half_as_ushort(h3) << 16);
        pl.x = (uint32_t)__half_as_ushort(l0) | ((uint32_t)__half_as_ushort(l1) << 16);
        pl.y = (uint32_t)__half_as_ushort(l2) | ((uint32_t)__half_as_ushort(l3) << 16);
        unsigned off = (unsigned)c * 256u + ((((unsigned)(q >> 1)) ^ (c & 7)) << 4) + (q & 1) * 8u;
        *(uint2*)(base + off) = ph;
        *(uint2*)(base + 8192 + off) = pl;
    }
}

// ================= main kernel (persistent, 2-deep register staging) =================
__global__ __launch_bounds__(NT_, 2)
void gsl_mma(const float* __restrict__ x,
             const float* __restrict__ g_trans, const float* __restrict__ b_trans,
             const float* __restrict__ g_gate,  const float* __restrict__ b_gate,
             const float* __restrict__ w_gate2, const float* __restrict__ b_gate2,
             const float* __restrict__ g_attn,  const float* __restrict__ b_attn,
             const float* __restrict__ w_attn2, const float* __restrict__ b_attn2,
             const float* __restrict__ agg_alpha,
             float* __restrict__ out, float* __restrict__ gate_out)
{
    extern __shared__ char smem[];
    const uint32_t sb = smem_u32(smem);
    const int t    = threadIdx.x;
    const int wid  = t >> 5;
    const int lane = t & 31;
    const int mw   = wid & 3;       // n-row within tile (4 rows)
    const int nw   = wid >> 2;      // 0: o 0..47, 1: o 48..79 (+heads)
    const int crow = t >> 5;        // 0..7: c row (mod 8) for staging
    const int q32  = t & 31;        // 16B group within 128m row
    const int bid  = blockIdx.x;

    // ---- fragment addressing (tile-invariant) ----
    const int l7   = lane & 7;
    const int koff = (lane >> 3) & 1;
    const int r16  = l7 + ((lane & 16) >> 1);
    uint32_t aBase[2];
    #pragma unroll
    for (int mt = 0; mt < 2; mt++)
        aBase[mt] = sb + SM_XB + r16 * 256 + ((((unsigned)(4 * mw + 2 * mt + koff)) ^ l7) << 4);
    const uint32_t bRowHi = sb + SM_W + r16 * 256;
    const uint32_t bRowLo = sb + SM_WLO + r16 * 256;

    const int qg = lane >> 2;
    const int c4 = lane & 3;
    float* WFs  = (float*)(smem + SM_WFS);
    float* Obuf = (float*)(smem + SM_OBUF);

    // ---- load W image once per CTA ----
    {
        uint4 wstg[6];
        #pragma unroll
        for (int i = 0; i < 6; i++) wstg[i] = g_Wimg[t + NT_ * i];
        uint4* d = (uint4*)smem;
        #pragma unroll
        for (int i = 0; i < 6; i++) d[t + NT_ * i] = wstg[i];
    }
    const float alpha = 1.0f / (1.0f + __expf(-agg_alpha[0]));

    // ---- LDG of chunk lc (32c x 128m fp32) into a 4x float4 register set ----
    auto ldg_chunk = [&](int lc, float4* stg) {
        int tl = bid + (lc >> 2) * NBLK;
        if (tl >= TILES) tl = bid;                    // clamped redundant load (tail)
        const float* src = x + (tl >> 10) * (C_ * N_ * K_) + (tl & 1023) * (TN_ * K_) + q32 * 4;
        const int cb = (lc & 3) * 32 + crow;
        #pragma unroll
        for (int i = 0; i < 4; i++)
            stg[i] = *(const float4*)(src + (size_t)(cb + 8 * i) * (N_ * K_));
    };

    // ---- prologue: chunks 0,1 into reg sets; convert chunk 0 -> buf 0 ----
    float4 stg[2][4];
    ldg_chunk(0, stg[0]);
    ldg_chunk(1, stg[1]);
    int lc = 2;                      // next chunk to LDG
    sts_chunk(smem + SM_XB, stg[0], crow, q32);
    __syncthreads();

    // ================= persistent tile loop =================
    for (int tile = bid; tile < TILES; tile += NBLK) {
        const int b  = tile >> 10;
        const int nb = (tile & 1023) * TN_;

        float acc[2][6][4];
        #pragma unroll
        for (int mt = 0; mt < 2; mt++)
            #pragma unroll
            for (int i = 0; i < 6; i++)
                #pragma unroll
                for (int j = 0; j < 4; j++) acc[mt][i][j] = 0.0f;

        // ---- mainloop: 4 steps of 32 c ----
        // invariant top of step s: buf s&1 ready (MMA input);
        //   stg[(s+1)&1] holds chunk s+1; stg[s&1] free.
        #pragma unroll
        for (int s = 0; s < 4; s++) {
            // LDG chunk s+2 into the free set (2 MMA-steps of slack)
            ldg_chunk(lc, stg[s & 1]);
            lc++;

            // MMA on fp16 buffer s&1
            const uint32_t xb = (uint32_t)(s & 1) * 16384u;
            #pragma unroll
            for (int g = 0; g < 2; g++) {
                const int st16 = 2 * s + g;
                const uint32_t cs = ((((unsigned)(2 * st16 + koff)) ^ l7) << 4);
                uint32_t ah[2][4];
                #pragma unroll
                for (int mt = 0; mt < 2; mt++)
                    LDSM_X4_T(ah[mt], aBase[mt] + xb + g * 4096u);
                if (nw == 0) {
                    #pragma unroll
                    for (int jp = 0; jp < 3; jp++) {
                        uint32_t bh[4];
                        LDSM_X4(bh, bRowHi + jp * 4096 + cs);
                        #pragma unroll
                        for (int mt = 0; mt < 2; mt++) {
                            MMA_F16(acc[mt][2 * jp],     ah[mt], bh[0], bh[1]);
                            MMA_F16(acc[mt][2 * jp + 1], ah[mt], bh[2], bh[3]);
                        }
                    }
                } else {
                    uint32_t al[2][4];
                    #pragma unroll
                    for (int mt = 0; mt < 2; mt++)
                        LDSM_X4_T(al[mt], aBase[mt] + xb + g * 4096u + 8192u);
                    {
                        uint32_t bh[4];
                        LDSM_X4(bh, bRowHi + 3 * 4096 + cs);
                        #pragma unroll
                        for (int mt = 0; mt < 2; mt++) {
                            MMA_F16(acc[mt][0], ah[mt], bh[0], bh[1]);
                            MMA_F16(acc[mt][1], ah[mt], bh[2], bh[3]);
                        }
                    }
                    {
                        uint32_t bh[4], bl[4];
                        LDSM_X4(bh, bRowHi + 4 * 4096 + cs);
                        LDSM_X4(bl, bRowLo + cs);
                        #pragma unroll
                        for (int mt = 0; mt < 2; mt++) {
                            MMA_F16(acc[mt][2], ah[mt], bh[0], bh[1]);
                            MMA_F16(acc[mt][3], ah[mt], bh[2], bh[3]);
                            MMA_F16(acc[mt][2], al[mt], bh[0], bh[1]);
                            MMA_F16(acc[mt][3], al[mt], bh[2], bh[3]);
                            MMA_F16(acc[mt][2], ah[mt], bl[0], bl[1]);
                            MMA_F16(acc[mt][3], ah[mt], bl[2], bl[3]);
                        }
                    }
                }
            }

            // convert chunk s+1 (LDG'd 2 steps ago; arrived) -> fp16 buf (s+1)&1
            sts_chunk(smem + SM_XB + (((s + 1) & 1) ? 16384 : 0), stg[(s + 1) & 1], crow, q32);
            __syncthreads();
        }

        // ================= in-register epilogue (R10-R14 verbatim) =================
        float WFreg[2][2];

        if (nw == 1) {
            float gl[2][2], al[2][2];
            const float bg2 = b_gate2[0], ba2 = b_attn2[0];
            #pragma unroll
            for (int mt = 0; mt < 2; mt++)
                #pragma unroll
                for (int rh = 0; rh < 2; rh++) {
                    float glp = 0.0f, alp = 0.0f;
                    #pragma unroll
                    for (int j = 0; j < 2; j++) {
                        int oc = 2 * c4 + j;
                        float yg = acc[mt][2][2 * rh + j];
                        float v = fmaf(g_gate[oc], yg, b_gate[oc]);
                        v = (v >= 0.0f) ? v : 0.2f * v;
                        glp = fmaf(w_gate2[oc], v, glp);
                        float ya = acc[mt][3][2 * rh + j];
                        float u = fmaf(g_attn[oc], ya, b_attn[oc]);
                        u = (u >= 0.0f) ? u : 0.2f * u;
                        alp = fmaf(w_attn2[oc], u, alp);
                    }
                    glp += __shfl_xor_sync(0xffffffffu, glp, 1);
                    glp += __shfl_xor_sync(0xffffffffu, glp, 2);
                    alp += __shfl_xor_sync(0xffffffffu, alp, 1);
                    alp += __shfl_xor_sync(0xffffffffu, alp, 2);
                    gl[mt][rh] = glp + bg2;
                    al[mt][rh] = alp + ba2;
                }
            float amax = fmaxf(fmaxf(al[0][0], al[0][1]), fmaxf(al[1][0], al[1][1]));
            #pragma unroll
            for (int s = 4; s <= 16; s <<= 1)
                amax = fmaxf(amax, __shfl_xor_sync(0xffffffffu, amax, s));
            float e[2][2];
            float S = 0.0f;
            #pragma unroll
            for (int mt = 0; mt < 2; mt++)
                #pragma unroll
                for (int rh = 0; rh < 2; rh++) {
                    e[mt][rh] = __expf(al[mt][rh] - amax);
                    S += e[mt][rh];
                }
            #pragma unroll
            for (int s = 4; s <= 16; s <<= 1)
                S += __shfl_xor_sync(0xffffffffu, S, s);
            const float invS = 1.0f / S;
            float wm[2][2];
            float Sm = 0.0f;
            #pragma unroll
            for (int mt = 0; mt < 2; mt++)
                #pragma unroll
                for (int rh = 0; rh < 2; rh++) {
                    float w = e[mt][rh] * invS;
                    wm[mt][rh] = (gl[mt][rh] >= 0.0f) ? w : 0.0f;
                    Sm += wm[mt][rh];
                }
            #pragma unroll
            for (int s = 4; s <= 16; s <<= 1)
                Sm += __shfl_xor_sync(0xffffffffu, Sm, s);
            const float rn = 1.0f / (Sm + 1e-6f);
            #pragma unroll
            for (int mt = 0; mt < 2; mt++)
                #pragma unroll
                for (int rh = 0; rh < 2; rh++)
                    WFreg[mt][rh] = wm[mt][rh] * rn;
            if (c4 == 0) {
                const int gbase = b * (N_ * K_) + (nb + mw) * K_;
                #pragma unroll
                for (int mt = 0; mt < 2; mt++)
                    #pragma unroll
                    for (int rh = 0; rh < 2; rh++) {
                        int k = qg + 8 * rh + 16 * mt;
                        WFs[mw * 32 + k] = WFreg[mt][rh];
                        gate_out[gbase + k] = gl[mt][rh];
                    }
            }
        }
        __syncthreads();

        if (nw == 0) {
            #pragma unroll
            for (int mt = 0; mt < 2; mt++)
                #pragma unroll
                for (int rh = 0; rh < 2; rh++)
                    WFreg[mt][rh] = WFs[mw * 32 + qg + 8 * rh + 16 * mt];
        }

        {
            const int ob  = nw * 48;
            const int njj = nw ? 2 : 6;
            for (int jj = 0; jj < njj; jj++) {
                #pragma unroll
                for (int par = 0; par < 2; par++) {
                    const int o = ob + 8 * jj + 2 * c4 + par;
                    const float g  = g_trans[o];
                    const float bb = b_trans[o];
                    float s = 0.0f, mx = -INFINITY;
                    #pragma unroll
                    for (int mt = 0; mt < 2; mt++)
                        #pragma unroll
                        for (int rh = 0; rh < 2; rh++) {
                            float y  = acc[mt][jj][2 * rh + par];
                            float tv = fmaf(g, y, bb);
                            tv = (tv >= 0.0f) ? tv : 0.2f * tv;
                            s  = fmaf(tv, WFreg[mt][rh], s);
                            mx = fmaxf(mx, tv);
                        }
                    #pragma unroll
                    for (int st = 4; st <= 16; st <<= 1) {
                        s += __shfl_xor_sync(0xffffffffu, s, st);
                        mx = fmaxf(mx, __shfl_xor_sync(0xffffffffu, mx, st));
                    }
                    if (qg == 0)
                        Obuf[o * 5 + mw] = alpha * s + (1.0f - alpha) * mx;
                }
            }
        }
        __syncthreads();

        if (t < 64) {
            float4 v;
            v.x = Obuf[t * 5 + 0];
            v.y = Obuf[t * 5 + 1];
            v.z = Obuf[t * 5 + 2];
            v.w = Obuf[t * 5 + 3];
            *(float4*)(out + (b * O_ + t) * N_ + nb) = v;
        }
        // no tail barrier: WFs/Obuf next writes are >=2 barriers away (mainloop)
    }
}

extern "C" void kernel_launch(void* const* d_in, const int* in_sizes, int n_in,
                              void* d_out, int out_size) {
    const float* x        = (const float*)d_in[0];
    const float* w_trans  = (const float*)d_in[1];
    const float* g_trans  = (const float*)d_in[2];
    const float* b_trans  = (const float*)d_in[3];
    const float* w_gate1  = (const float*)d_in[4];
    const float* g_gate   = (const float*)d_in[5];
    const float* b_gate   = (const float*)d_in[6];
    const float* w_gate2  = (const float*)d_in[7];
    const float* b_gate2  = (const float*)d_in[8];
    const float* w_attn1  = (const float*)d_in[9];
    const float* g_attn   = (const float*)d_in[10];
    const float* b_attn   = (const float*)d_in[11];
    const float* w_attn2  = (const float*)d_in[12];
    const float* b_attn2  = (const float*)d_in[13];
    const float* agg_alpha= (const float*)d_in[14];

    float* out      = (float*)d_out;                  // [B,O,N]
    float* gate_out = out + (size_t)B_ * O_ * N_;     // [B,1,N,K]

    cudaFuncSetAttribute(gsl_mma, cudaFuncAttributeMaxDynamicSharedMemorySize, SM_TOTAL);

    prep_b<<<(NH_ * C_ + 255) / 256, 256>>>(w_trans, w_gate1, w_attn1);
    gsl_mma<<<NBLK, NT_, SM_TOTAL>>>(
        x, g_trans, b_trans, g_gate, b_gate, w_gate2, b_gate2,
        g_attn, b_attn, w_attn2, b_attn2, agg_alpha, out, gate_out);
}